// round 7
// baseline (speedup 1.0000x reference)
#include <cuda_runtime.h>
#include <cstdint>

// Problem constants
#define B_SZ   1024
#define F_SZ   784
#define OUT_F  1024
#define OR_T   32
#define AND_T  16
#define NLIT   (1 + 2 * F_SZ)   // 1569 literals
#define NBG    (B_SZ / 32)      // 32 words per literal row = 128 B
#define TBL_WORDS (NLIT * NBG)  // 200832 B (L1D/L2 resident)

__device__ __align__(16) uint32_t g_T[TBL_WORDS];

// ---------------------------------------------------------------------------
// Pack kernel: grid (25, 32), 128 threads. Coalesced 32x32 tile load ->
// smem transpose -> ballot per feature. (Empirically ~1us.)
// ---------------------------------------------------------------------------
__global__ __launch_bounds__(128) void pack_kernel(const float* __restrict__ x) {
    __shared__ float tile[32][33];

    const int ft  = blockIdx.x;
    const int bg  = blockIdx.y;
    const int tid = threadIdx.x;
    const int f0  = ft * 32;

    const int c  = tid & 31;
    const int r0 = tid >> 5;
    #pragma unroll
    for (int r = r0; r < 32; r += 4) {
        const int f = f0 + c;
        tile[r][c] = (f < F_SZ) ? x[(size_t)(bg * 32 + r) * F_SZ + f] : 0.0f;
    }
    __syncthreads();

    const int lane = tid & 31;
    const int w    = tid >> 5;
    #pragma unroll
    for (int ff = w; ff < 32; ff += 4) {
        const int f = f0 + ff;
        if (f >= F_SZ) break;
        uint32_t m = __ballot_sync(0xFFFFFFFFu, tile[lane][ff] != 0.0f);
        if (lane == 0) {
            g_T[(size_t)(1 + f) * NBG + bg]        = m;
            g_T[(size_t)(1 + F_SZ + f) * NBG + bg] = ~m;
        }
    }
    if (ft == 0 && tid == 0) g_T[bg] = 0xFFFFFFFFu;
}

// ---------------------------------------------------------------------------
// Logic kernel: 512 blocks x 512 threads, 2 outputs per block.
// Warp = (output, 4-term slice). Lane = (tg, bc): tg = lane>>3 picks the term
// within the slice, bc = lane&7 picks a 128-batch uint4 chunk of the table
// row. Each gather is an LDG.128 retiring 512B/warp (4 x 128B segments).
// Cross-tg OR via shfl; cross-slice OR via smem at store time.
// ---------------------------------------------------------------------------
#define OPB 2                       // outputs per block
#define NTHREADS 512

__global__ __launch_bounds__(NTHREADS, 2) void logic_kernel(
    const int* __restrict__ weights, float* __restrict__ out) {

    __shared__ uint32_t sw[OPB * OR_T * AND_T];   // 4 KB weights
    __shared__ uint4    resb[OPB * 8][8];         // [out][slice][bc], 2 KB

    const int tid   = threadIdx.x;
    const int oBase = blockIdx.x * OPB;

    // Stage weights (256 x uint4, coalesced)
    if (tid < OPB * OR_T * AND_T / 4)
        ((uint4*)sw)[tid] = ((const uint4*)(weights + (size_t)oBase * OR_T * AND_T))[tid];
    __syncthreads();

    const int wid   = tid >> 5;        // 0..15
    const int lane  = tid & 31;
    const int o     = wid >> 3;        // output within block (0..1)
    const int slice = wid & 7;         // which 4-term slice (0..7)
    const int tg    = lane >> 3;       // term within slice (0..3)
    const int bc    = lane & 7;        // 128-batch chunk (0..7)
    const int term  = slice * 4 + tg;  // 0..31

    // This term's 16 weight indices (4 x uniform-per-tg LDS.128)
    const uint4* twp = (const uint4*)(sw + o * (OR_T * AND_T) + term * AND_T);
    const uint4 w0 = twp[0], w1 = twp[1], w2 = twp[2], w3 = twp[3];

    const uint32_t orw = (w0.x | w0.y | w0.z | w0.w) | (w1.x | w1.y | w1.z | w1.w)
                       | (w2.x | w2.y | w2.z | w2.w) | (w3.x | w3.y | w3.z | w3.w);

    const char* tb = (const char*)g_T + (size_t)bc * 16;   // lane's 16B column
    #define GV(i) __ldg((const uint4*)(tb + (size_t)(i) * 128))

    // 16 independent LDG.128 gathers, two AND chains
    uint4 a = GV(w0.x), b = GV(w0.y), c = GV(w0.z), d = GV(w0.w);
    uint4 m0, m1;
    m0.x = a.x & c.x; m0.y = a.y & c.y; m0.z = a.z & c.z; m0.w = a.w & c.w;
    m1.x = b.x & d.x; m1.y = b.y & d.y; m1.z = b.z & d.z; m1.w = b.w & d.w;
    a = GV(w1.x); b = GV(w1.y); c = GV(w1.z); d = GV(w1.w);
    m0.x &= a.x & c.x; m0.y &= a.y & c.y; m0.z &= a.z & c.z; m0.w &= a.w & c.w;
    m1.x &= b.x & d.x; m1.y &= b.y & d.y; m1.z &= b.z & d.z; m1.w &= b.w & d.w;
    a = GV(w2.x); b = GV(w2.y); c = GV(w2.z); d = GV(w2.w);
    m0.x &= a.x & c.x; m0.y &= a.y & c.y; m0.z &= a.z & c.z; m0.w &= a.w & c.w;
    m1.x &= b.x & d.x; m1.y &= b.y & d.y; m1.z &= b.z & d.z; m1.w &= b.w & d.w;
    a = GV(w3.x); b = GV(w3.y); c = GV(w3.z); d = GV(w3.w);
    m0.x &= a.x & c.x; m0.y &= a.y & c.y; m0.z &= a.z & c.z; m0.w &= a.w & c.w;
    m1.x &= b.x & d.x; m1.y &= b.y & d.y; m1.z &= b.z & d.z; m1.w &= b.w & d.w;
    #undef GV

    const uint32_t sel = (orw != 0) ? 0xFFFFFFFFu : 0u;  // all-zero term masked
    uint4 m;
    m.x = m0.x & m1.x & sel; m.y = m0.y & m1.y & sel;
    m.z = m0.z & m1.z & sel; m.w = m0.w & m1.w & sel;

    // OR-reduce across the 4 term-groups (lanes +-8, +-16)
    m.x |= __shfl_xor_sync(0xFFFFFFFFu, m.x, 8);
    m.y |= __shfl_xor_sync(0xFFFFFFFFu, m.y, 8);
    m.z |= __shfl_xor_sync(0xFFFFFFFFu, m.z, 8);
    m.w |= __shfl_xor_sync(0xFFFFFFFFu, m.w, 8);
    m.x |= __shfl_xor_sync(0xFFFFFFFFu, m.x, 16);
    m.y |= __shfl_xor_sync(0xFFFFFFFFu, m.y, 16);
    m.z |= __shfl_xor_sync(0xFFFFFFFFu, m.z, 16);
    m.w |= __shfl_xor_sync(0xFFFFFFFFu, m.w, 16);

    if (lane < 8) resb[o * 8 + slice][bc] = m;
    __syncthreads();

    // Store: thread handles batches tid and tid+512; per batch, OPB floats.
    #pragma unroll
    for (int b = tid; b < B_SZ; b += NTHREADS) {
        const int chunk = b >> 7;          // bc
        const int wsel  = (b >> 5) & 3;    // word within uint4
        const int j     = b & 31;
        float2 v;
        #pragma unroll
        for (int oo = 0; oo < OPB; ++oo) {
            uint32_t r = 0;
            #pragma unroll
            for (int s = 0; s < 8; ++s) {
                const uint4 u = resb[oo * 8 + s][chunk];
                r |= (wsel == 0) ? u.x : (wsel == 1) ? u.y : (wsel == 2) ? u.z : u.w;
            }
            ((float*)&v)[oo] = (float)((r >> j) & 1u);
        }
        *(float2*)(out + (size_t)b * OUT_F + oBase) = v;
    }
}

// ---------------------------------------------------------------------------
extern "C" void kernel_launch(void* const* d_in, const int* in_sizes, int n_in,
                              void* d_out, int out_size) {
    const float* x       = (const float*)d_in[0];   // (1024, 784) float32
    const int*   weights = (const int*)d_in[1];     // (1024, 32, 16) int32
    float*       out     = (float*)d_out;           // (1024, 1024) float32

    dim3 pgrid(25, 32);
    pack_kernel<<<pgrid, 128>>>(x);
    logic_kernel<<<OUT_F / OPB, NTHREADS>>>(weights, out);
}

// round 8
// speedup vs baseline: 1.0667x; 1.0667x over previous
#include <cuda_runtime.h>
#include <cstdint>

// Problem constants
#define B_SZ   1024
#define F_SZ   784
#define OUT_F  1024
#define OR_T   32
#define AND_T  16
#define NLIT   (1 + 2 * F_SZ)   // 1569 literals
#define NBG    (B_SZ / 32)      // 32 words per literal row = 128 B
#define TBL_WORDS (NLIT * NBG)  // 200832 B (L1D-resident per SM)

__device__ __align__(16) uint32_t g_T[TBL_WORDS];

// ---------------------------------------------------------------------------
// Pack kernel: grid (25, 32), 128 threads. Coalesced 32x32 tile load ->
// smem transpose -> ballot per feature. (~1us)
// ---------------------------------------------------------------------------
__global__ __launch_bounds__(128) void pack_kernel(const float* __restrict__ x) {
    __shared__ float tile[32][33];

    const int ft  = blockIdx.x;
    const int bg  = blockIdx.y;
    const int tid = threadIdx.x;
    const int f0  = ft * 32;

    const int c  = tid & 31;
    const int r0 = tid >> 5;
    #pragma unroll
    for (int r = r0; r < 32; r += 4) {
        const int f = f0 + c;
        tile[r][c] = (f < F_SZ) ? x[(size_t)(bg * 32 + r) * F_SZ + f] : 0.0f;
    }
    __syncthreads();

    const int lane = tid & 31;
    const int w    = tid >> 5;
    #pragma unroll
    for (int ff = w; ff < 32; ff += 4) {
        const int f = f0 + ff;
        if (f >= F_SZ) break;
        uint32_t m = __ballot_sync(0xFFFFFFFFu, tile[lane][ff] != 0.0f);
        if (lane == 0) {
            g_T[(size_t)(1 + f) * NBG + bg]        = m;
            g_T[(size_t)(1 + F_SZ + f) * NBG + bg] = ~m;
        }
    }
    if (ft == 0 && tid == 0) g_T[bg] = 0xFFFFFFFFu;
}

// ---------------------------------------------------------------------------
// Logic kernel: 256 blocks x 512 threads, 2 CTAs/SM.
// Phase 0: weights LDG + dependency-free L1 prefetch sweep of the table
//          (25 independent uint4 __ldg per thread -> misses pipeline at
//          queue-limited rate instead of AND-chain-limited rate).
// Phase 1: gather from L1 (warp quad per output, 8 OR-terms each).
// ---------------------------------------------------------------------------
#define OUTS_PER_BLOCK 4
#define NTHREADS 512
#define W_WORDS (OUTS_PER_BLOCK * OR_T * AND_T)   // 2048 words = 8 KB

__global__ __launch_bounds__(NTHREADS, 2) void logic_kernel(
    const int* __restrict__ weights, float* __restrict__ out) {

    __shared__ uint32_t sw[W_WORDS];                       // 8 KB weights
    __shared__ uint32_t resb[OUTS_PER_BLOCK * 4 * NBG];    // 2 KB results

    const int tid   = threadIdx.x;
    const int oBase = blockIdx.x * OUTS_PER_BLOCK;

    // Weights first (so their lines arrive before the prefetch flood)
    {
        const uint4* wsrc = (const uint4*)(weights + (size_t)oBase * OR_T * AND_T);
        ((uint4*)sw)[tid] = wsrc[tid];                     // 512 x LDG.128
    }

    // Prefetch sweep: pull the whole table into L1 with max MLP.
    {
        const uint4* t4 = (const uint4*)g_T;
        uint4 acc = make_uint4(0u, 0u, 0u, 0u);
        #pragma unroll 5
        for (int i = tid; i < TBL_WORDS / 4; i += NTHREADS) {   // ~25 iters
            const uint4 v = __ldg(t4 + i);
            acc.x |= v.x; acc.y |= v.y; acc.z |= v.z; acc.w |= v.w;
        }
        // Sink: force materialization without side effects
        asm volatile("" :: "r"(acc.x), "r"(acc.y), "r"(acc.z), "r"(acc.w));
    }
    __syncthreads();

    const int wid  = tid >> 5;                 // 0..15
    const int lane = tid & 31;                 // batch-group
    const int wi   = wid >> 2;                 // output within block (0..3)
    const int q    = wid & 3;                  // term quarter

    const uint4* tw4 = (const uint4*)(sw + wi * (OR_T * AND_T) + q * (8 * AND_T));

    uint32_t res = 0;
    #pragma unroll 2
    for (int t = 0; t < 8; ++t) {
        uint32_t m0 = 0xFFFFFFFFu, m1 = 0xFFFFFFFFu;
        uint32_t orw = 0;
        #pragma unroll
        for (int k4 = 0; k4 < 4; ++k4) {
            const uint4 w4 = tw4[t * 4 + k4];              // uniform LDS.128
            orw |= (w4.x | w4.y | w4.z | w4.w);
            m0 &= __ldg(&g_T[w4.x * NBG + lane]);          // L1 hits
            m1 &= __ldg(&g_T[w4.y * NBG + lane]);
            m0 &= __ldg(&g_T[w4.z * NBG + lane]);
            m1 &= __ldg(&g_T[w4.w * NBG + lane]);
        }
        if (orw != 0) res |= (m0 & m1);
    }
    resb[(wi * 4 + q) * NBG + lane] = res;
    __syncthreads();

    // Store: per batch, 4 contiguous floats (one float4), OR over the 4 quads
    #pragma unroll
    for (int b = tid; b < B_SZ; b += NTHREADS) {           // 2 iterations
        const int bg = b >> 5;
        const int j  = b & 31;
        float4 v;
        #define GETBIT(ow) ((((resb[((ow)*4+0)*NBG + bg] | resb[((ow)*4+1)*NBG + bg] | \
                               resb[((ow)*4+2)*NBG + bg] | resb[((ow)*4+3)*NBG + bg]) >> j) & 1u))
        v.x = (float)GETBIT(0); v.y = (float)GETBIT(1);
        v.z = (float)GETBIT(2); v.w = (float)GETBIT(3);
        #undef GETBIT
        *(float4*)(out + (size_t)b * OUT_F + oBase) = v;
    }
}

// ---------------------------------------------------------------------------
extern "C" void kernel_launch(void* const* d_in, const int* in_sizes, int n_in,
                              void* d_out, int out_size) {
    const float* x       = (const float*)d_in[0];   // (1024, 784) float32
    const int*   weights = (const int*)d_in[1];     // (1024, 32, 16) int32
    float*       out     = (float*)d_out;           // (1024, 1024) float32

    // Max-L1 carveout so the 200KB table is fully cacheable (idempotent,
    // not a stream op -> capture-safe).
    cudaFuncSetAttribute(logic_kernel,
                         cudaFuncAttributePreferredSharedMemoryCarveout,
                         cudaSharedmemCarveoutMaxL1);

    dim3 pgrid(25, 32);
    pack_kernel<<<pgrid, 128>>>(x);
    logic_kernel<<<OUT_F / OUTS_PER_BLOCK, NTHREADS>>>(weights, out);
}

// round 9
// speedup vs baseline: 1.2222x; 1.1458x over previous
#include <cuda_runtime.h>
#include <cstdint>

// Problem constants
#define B_SZ   1024
#define F_SZ   784
#define OUT_F  1024
#define OR_T   32
#define AND_T  16
#define NLIT   (1 + 2 * F_SZ)   // 1569 literals
#define NBG    (B_SZ / 32)      // 32 words per literal row = 128 B
#define TBL_WORDS (NLIT * NBG)  // 50208 words = 200832 B
#define TBL_BYTES (TBL_WORDS * 4)

#define OUTS_PER_BLOCK 8
#define NTHREADS 512
#define W_WORDS (OUTS_PER_BLOCK * OR_T * AND_T)     // 4096 words = 16 KB
#define RES_WORDS (OUTS_PER_BLOCK * 2 * NBG)        // 512 words
#define MBAR_OFF_W (TBL_WORDS + W_WORDS + RES_WORDS + 4)
#define SMEM_BYTES ((MBAR_OFF_W + 4) * 4)           // ~219.3 KB

__device__ __align__(16) uint32_t g_T[TBL_WORDS];

// ---------------------------------------------------------------------------
// Pack kernel: grid (25, 32), 128 threads (empirically ~1us).
// ---------------------------------------------------------------------------
__global__ __launch_bounds__(128) void pack_kernel(const float* __restrict__ x) {
    __shared__ float tile[32][33];

    const int ft  = blockIdx.x;
    const int bg  = blockIdx.y;
    const int tid = threadIdx.x;
    const int f0  = ft * 32;

    const int c  = tid & 31;
    const int r0 = tid >> 5;
    #pragma unroll
    for (int r = r0; r < 32; r += 4) {
        const int f = f0 + c;
        tile[r][c] = (f < F_SZ) ? x[(size_t)(bg * 32 + r) * F_SZ + f] : 0.0f;
    }
    __syncthreads();

    const int lane = tid & 31;
    const int w    = tid >> 5;
    #pragma unroll
    for (int ff = w; ff < 32; ff += 4) {
        const int f = f0 + ff;
        if (f >= F_SZ) break;
        uint32_t m = __ballot_sync(0xFFFFFFFFu, tile[lane][ff] != 0.0f);
        if (lane == 0) {
            g_T[(size_t)(1 + f) * NBG + bg]        = m;
            g_T[(size_t)(1 + F_SZ + f) * NBG + bg] = ~m;
        }
    }
    if (ft == 0 && tid == 0) g_T[bg] = 0xFFFFFFFFu;
}

// ---------------------------------------------------------------------------
// Logic kernel: 128 blocks x 512 threads (R4 architecture + LDS.64 gather).
//  - TMA bulk fill of the 200KB table into smem; weights staged concurrently.
//  - Warp pair per output (term halves h=0/1). Lane = (th = lane>>4 picks one
//    of 2 terms per pass, bgp = lane&15 picks a uint2 = 2 batch-groups).
//    Gathers are LDS.64: 2 terms x 128B per instruction, conflict-free.
// ---------------------------------------------------------------------------
__global__ __launch_bounds__(NTHREADS, 1) void logic_kernel(
    const int* __restrict__ weights, float* __restrict__ out) {

    extern __shared__ uint32_t smem[];
    uint32_t* sT   = smem;                     // table (50208 words)
    uint32_t* sw   = smem + TBL_WORDS;         // weights (4096 words)
    uint32_t* resb = sw + W_WORDS;             // results (512 words)
    uint32_t  mbar_addr;
    {
        uint64_t* mb64 = (uint64_t*)(smem + MBAR_OFF_W);
        asm("{ .reg .u64 t; cvta.to.shared.u64 t, %1; cvt.u32.u64 %0, t; }"
            : "=r"(mbar_addr) : "l"((void*)mb64));
    }

    const int tid   = threadIdx.x;
    const int oBase = blockIdx.x * OUTS_PER_BLOCK;

    if (tid == 0) {
        asm volatile("mbarrier.init.shared.b64 [%0], 1;" :: "r"(mbar_addr) : "memory");
    }
    __syncthreads();

    if (tid == 0) {
        asm volatile("mbarrier.arrive.expect_tx.shared.b64 _, [%0], %1;"
                     :: "r"(mbar_addr), "r"((uint32_t)TBL_BYTES) : "memory");
        const char* gsrc = (const char*)g_T;
        uint32_t sdst;
        asm("{ .reg .u64 t; cvta.to.shared.u64 t, %1; cvt.u32.u64 %0, t; }"
            : "=r"(sdst) : "l"((void*)sT));
        const uint32_t chunk = TBL_BYTES / 8;   // 25104 B, multiple of 16
        #pragma unroll
        for (int i = 0; i < 8; ++i) {
            asm volatile(
                "cp.async.bulk.shared::cta.global.mbarrier::complete_tx::bytes "
                "[%0], [%1], %2, [%3];"
                :: "r"(sdst + i * chunk), "l"(gsrc + i * chunk),
                   "r"(chunk), "r"(mbar_addr) : "memory");
        }
    }

    // Stage this block's weights while the DMA runs (2 uint4 per thread)
    {
        const uint4* wsrc = (const uint4*)(weights + (size_t)oBase * OR_T * AND_T);
        uint4* wdst = (uint4*)sw;
        wdst[tid]       = wsrc[tid];
        wdst[tid + 512] = wsrc[tid + 512];
    }
    __syncthreads();

    // Wait for the table DMA
    {
        uint32_t done;
        asm volatile(
            "{\n\t.reg .pred p;\n\t"
            "mbarrier.try_wait.parity.acquire.cta.shared::cta.b64 p, [%1], 0;\n\t"
            "selp.b32 %0, 1, 0, p;\n\t}"
            : "=r"(done) : "r"(mbar_addr) : "memory");
        if (!done) {
            asm volatile(
                "{\n\t.reg .pred P1;\n\t"
                "WL_%=:\n\t"
                "mbarrier.try_wait.parity.acquire.cta.shared::cta.b64 P1, [%0], 0, 0x989680;\n\t"
                "@P1 bra.uni WD_%=;\n\t"
                "bra.uni WL_%=;\n\t"
                "WD_%=:\n\t}"
                :: "r"(mbar_addr) : "memory");
        }
    }

    const int wid  = tid >> 5;                 // 0..15
    const int lane = tid & 31;
    const int o    = wid >> 1;                 // output within block (0..7)
    const int h    = wid & 1;                  // term half (0..1)
    const int th   = lane >> 4;                // term selector within pass
    const int bgp  = lane & 15;                // batch-group pair (uint2)

    const uint32_t* swb = sw + o * (OR_T * AND_T);
    const uint2*    sT2 = (const uint2*)sT;

    uint2 res = make_uint2(0u, 0u);
    #pragma unroll
    for (int t2 = 0; t2 < 8; ++t2) {
        const int t = h * 16 + t2 * 2 + th;             // this lane's term
        const uint4* tw4 = (const uint4*)(swb + t * AND_T);
        uint2 m0 = make_uint2(~0u, ~0u), m1 = make_uint2(~0u, ~0u);
        uint32_t orw = 0;
        #pragma unroll
        for (int k4 = 0; k4 < 4; ++k4) {
            const uint4 w4 = tw4[k4];                   // broadcast LDS.128
            orw |= (w4.x | w4.y | w4.z | w4.w);
            const uint2 a = sT2[w4.x * 16 + bgp];       // LDS.64 gathers
            const uint2 b = sT2[w4.y * 16 + bgp];
            const uint2 c = sT2[w4.z * 16 + bgp];
            const uint2 d = sT2[w4.w * 16 + bgp];
            m0.x &= a.x & c.x;  m0.y &= a.y & c.y;
            m1.x &= b.x & d.x;  m1.y &= b.y & d.y;
        }
        const uint32_t sel = (orw != 0) ? ~0u : 0u;     // all-zero term masked
        res.x |= m0.x & m1.x & sel;
        res.y |= m0.y & m1.y & sel;
    }
    // OR across th (lanes l <-> l+16 share bgp)
    res.x |= __shfl_xor_sync(0xFFFFFFFFu, res.x, 16);
    res.y |= __shfl_xor_sync(0xFFFFFFFFu, res.y, 16);

    if (lane < 16) {
        resb[(o * 2 + h) * NBG + bgp * 2]     = res.x;  // bg even
        resb[(o * 2 + h) * NBG + bgp * 2 + 1] = res.y;  // bg odd
    }
    __syncthreads();

    // Store: per batch, 8 contiguous floats (two float4), OR over term halves
    #pragma unroll
    for (int b = tid; b < B_SZ; b += NTHREADS) {        // 2 iterations
        const int bg = b >> 5;
        const int j  = b & 31;
        float4 v0, v1;
        #define GETBIT(ow) ((((resb[((ow)*2+0)*NBG + bg] | \
                               resb[((ow)*2+1)*NBG + bg]) >> j) & 1u))
        v0.x = (float)GETBIT(0); v0.y = (float)GETBIT(1);
        v0.z = (float)GETBIT(2); v0.w = (float)GETBIT(3);
        v1.x = (float)GETBIT(4); v1.y = (float)GETBIT(5);
        v1.z = (float)GETBIT(6); v1.w = (float)GETBIT(7);
        #undef GETBIT
        float4* dst = (float4*)(out + (size_t)b * OUT_F + oBase);
        dst[0] = v0;
        dst[1] = v1;
    }
}

// ---------------------------------------------------------------------------
extern "C" void kernel_launch(void* const* d_in, const int* in_sizes, int n_in,
                              void* d_out, int out_size) {
    const float* x       = (const float*)d_in[0];   // (1024, 784) float32
    const int*   weights = (const int*)d_in[1];     // (1024, 32, 16) int32
    float*       out     = (float*)d_out;           // (1024, 1024) float32

    cudaFuncSetAttribute(logic_kernel,
                         cudaFuncAttributeMaxDynamicSharedMemorySize, SMEM_BYTES);

    dim3 pgrid(25, 32);
    pack_kernel<<<pgrid, 128>>>(x);
    logic_kernel<<<OUT_F / OUTS_PER_BLOCK, NTHREADS, SMEM_BYTES>>>(weights, out);
}